// round 15
// baseline (speedup 1.0000x reference)
#include <cuda_runtime.h>
#include <cuda_bf16.h>
#include <cstdint>

#define NN 50000
#define EE 800000
#define DD 64
#define LL 3
#define RR 4

// ---------------- device scratch (static: no allocations allowed) ----------------
__device__ float g_xproj[NN * DD];
__device__ float g_p[NN * DD];
__device__ float g_tbar[NN * DD];
__device__ float g_hnew[NN * DD];
__device__ unsigned char g_keepb[LL * NN];
__device__ int g_deg[NN];
__device__ int g_rowptr[NN + 1];
__device__ int g_cursor[NN];
__device__ int g_col[EE];
__device__ float g_bnsum[LL * DD];
__device__ float g_bnsq[LL * DD];
__device__ int g_found32;  // sticky: 1 if edge_index is int32. Never reset -> deterministic.

// ---------------- generic helpers ----------------
__device__ __forceinline__ unsigned rotl32(unsigned v, int s) {
    return (v << s) | (v >> (32 - s));
}

__device__ void threefry(unsigned k0, unsigned k1, unsigned x0, unsigned x1,
                         unsigned& o0, unsigned& o1) {
    unsigned ks2 = k0 ^ k1 ^ 0x1BD11BDAu;
    x0 += k0; x1 += k1;
#define TFR(r) { x0 += x1; x1 = rotl32(x1, r); x1 ^= x0; }
    TFR(13) TFR(15) TFR(26) TFR(6)   x0 += k1;  x1 += ks2 + 1u;
    TFR(17) TFR(29) TFR(16) TFR(24)  x0 += ks2; x1 += k0 + 2u;
    TFR(13) TFR(15) TFR(26) TFR(6)   x0 += k0;  x1 += k1 + 3u;
    TFR(17) TFR(29) TFR(16) TFR(24)  x0 += k1;  x1 += ks2 + 4u;
    TFR(13) TFR(15) TFR(26) TFR(6)   x0 += ks2; x1 += k0 + 5u;
#undef TFR
    o0 = x0; o1 = x1;
}

__device__ __forceinline__ float mishf(float x) {
    float sp = fmaxf(x, 0.f) + log1pf(expf(-fabsf(x)));
    return x * tanhf(sp);
}

__device__ __forceinline__ int edge_val(const void* ei, int idx) {
    if (g_found32 == 0) return (int)((const long long*)ei)[idx];
    return ((const int*)ei)[idx];
}

// ---------------- init + dtype detect + bn zero + dropout masks -------------------
__global__ void initdetect_mask(const unsigned* w) {
    int i = blockIdx.x * blockDim.x + threadIdx.x;
    if (i < EE && w[2 * i + 1] != 0u) g_found32 = 1;
    if (i < NN) g_deg[i] = 0;
    if (i < LL * DD) { g_bnsum[i] = 0.f; g_bnsq[i] = 0.f; }
    if (i < LL * NN) {
        int lay = i / NN, n = i % NN;
        unsigned fk0, fk1;
        threefry(0u, 42u, 0u, (unsigned)lay, fk0, fk1);
        unsigned byte = 0;
#pragma unroll
        for (int r = 0; r < RR; r++) {
            unsigned o0, o1;
            threefry(fk0, fk1, 0u, (unsigned)(r * NN + n), o0, o1);
            unsigned draw = o0 ^ o1;
            float u = __uint_as_float((draw >> 9) | 0x3f800000u) - 1.0f;
            if (!(u < 0.2f)) byte |= (1u << r);
        }
        g_keepb[i] = (unsigned char)byte;
    }
}

// ---------------- CSR build ----------------
__global__ void count_deg(const void* ei) {
    int e = blockIdx.x * blockDim.x + threadIdx.x;
    if (e < EE) atomicAdd(&g_deg[edge_val(ei, EE + e)], 1);
}

__global__ __launch_bounds__(1024) void scan_one() {
    __shared__ int s[1024];
    __shared__ int carry_s;
    int t = threadIdx.x;
    if (t == 0) carry_s = 0;
    __syncthreads();
    for (int c = 0; c < 13; c++) {
        int base = c * 4096 + t * 4;
        int v0 = (base + 0 < NN) ? g_deg[base + 0] : 0;
        int v1 = (base + 1 < NN) ? g_deg[base + 1] : 0;
        int v2 = (base + 2 < NN) ? g_deg[base + 2] : 0;
        int v3 = (base + 3 < NN) ? g_deg[base + 3] : 0;
        int sum = v0 + v1 + v2 + v3;
        s[t] = sum;
        __syncthreads();
#pragma unroll
        for (int off = 1; off < 1024; off <<= 1) {
            int x = (t >= off) ? s[t - off] : 0;
            __syncthreads();
            s[t] += x;
            __syncthreads();
        }
        int excl = s[t] - sum + carry_s;
        if (base + 0 < NN) { g_rowptr[base + 0] = excl;            g_cursor[base + 0] = excl; }
        if (base + 1 < NN) { g_rowptr[base + 1] = excl + v0;       g_cursor[base + 1] = excl + v0; }
        if (base + 2 < NN) { g_rowptr[base + 2] = excl + v0 + v1;  g_cursor[base + 2] = excl + v0 + v1; }
        if (base + 3 < NN) { g_rowptr[base + 3] = excl + v0 + v1 + v2;
                             g_cursor[base + 3] = excl + v0 + v1 + v2; }
        __syncthreads();
        if (t == 0) carry_s += s[1023];
        __syncthreads();
    }
    if (t == 0) g_rowptr[NN] = EE;
}

__global__ void fill_csr(const void* ei) {
    int e = blockIdx.x * blockDim.x + threadIdx.x;
    if (e < EE) {
        int dst = edge_val(ei, EE + e);
        int src = edge_val(ei, e);
        int pos = atomicAdd(&g_cursor[dst], 1);
        g_col[pos] = src;
    }
}

// ---------------- mma.sync GEMM: (M x 64) @ (64 x 64), split-bf16, 64-row tile ----
// D = Xh@Wh + Xh@Wl + Xl@Wh via mma.sync.m16n8k16 bf16 (HMMA).
// 256 threads = 8 warps; warp w: m16 slice (w>>1), n-half (w&1)*32.
// mode 0: Y = X@W ; 1: +b ; 2: mish(+b) ; 3: +b + BN(res) + bn stats
// bnin >= 0: X transformed mish((x-mu)*rstd) on load (modes 0/1/2); in mode 3 the
// transform applies to res instead.
#define STR 144            /* smem row stride bytes: 72 bf16 — conflict-free frags */
#define SM_ST 0            /* st[0..63]=mu [64..127]=rstd [128..191]=bias (1024 B) */
#define SM_A_H 1024
#define SM_A_L (SM_A_H + 64 * STR)       /* 10240 */
#define SM_B_H (SM_A_L + 64 * STR)       /* 19456 */
#define SM_B_L (SM_B_H + 64 * STR)       /* 28672 */
#define SM_TOTAL (SM_B_L + 64 * STR)     /* 37888 -> 6 CTAs/SM */
#define SM_STAGE SM_A_H                  /* 64 x 68 floats = 17408 B, fits A_H+A_L */

__device__ __forceinline__ void mma16816(float* c, uint32_t a0, uint32_t a1,
                                         uint32_t a2, uint32_t a3,
                                         uint32_t b0, uint32_t b1) {
    asm volatile(
        "mma.sync.aligned.m16n8k16.row.col.f32.bf16.bf16.f32 "
        "{%0,%1,%2,%3}, {%4,%5,%6,%7}, {%8,%9}, {%0,%1,%2,%3};"
        : "+f"(c[0]), "+f"(c[1]), "+f"(c[2]), "+f"(c[3])
        : "r"(a0), "r"(a1), "r"(a2), "r"(a3), "r"(b0), "r"(b1));
}

__device__ __forceinline__ uint32_t pack_hi(float x, float y, float& lx, float& ly) {
    __nv_bfloat16 hx = __float2bfloat16(x);
    __nv_bfloat16 hy = __float2bfloat16(y);
    lx = x - __bfloat162float(hx);
    ly = y - __bfloat162float(hy);
    __nv_bfloat162 p = __halves2bfloat162(hx, hy);
    return *(uint32_t*)&p;
}
__device__ __forceinline__ uint32_t pack_bf2(float x, float y) {
    __nv_bfloat162 p = __floats2bfloat162_rn(x, y);
    return *(uint32_t*)&p;
}

__global__ __launch_bounds__(256) void mma_gemm(
    const float* __restrict__ X, const float* __restrict__ W,
    const float* __restrict__ bias, const float* __restrict__ res,
    float* __restrict__ Y, int M, int mode, int bnin, int layer) {
    extern __shared__ char smem[];
    int t = threadIdx.x;
    int w = t >> 5, lane = t & 31, g = lane >> 2, tid = lane & 3;
    int row0 = blockIdx.x * 64;
    float* st = (float*)(smem + SM_ST);

    if (t < 64) {
        if (bnin >= 0) {
            float mu = g_bnsum[bnin * DD + t] * (1.f / NN);
            float var = g_bnsq[bnin * DD + t] * (1.f / NN) - mu * mu;
            st[t] = mu;
            st[64 + t] = rsqrtf(var + 1e-5f);
        }
        st[128 + t] = bias ? bias[t] : 0.f;
    }
    __syncthreads();

    // A tile: 64 rows x 32 k-pairs; optional BN-mish on load
    for (int idx = t; idx < 64 * 32; idx += 256) {
        int r = idx >> 5, kp = idx & 31;
        int gr = row0 + r;
        float2 xv = (gr < M) ? *(const float2*)&X[gr * 64 + kp * 2]
                             : make_float2(0.f, 0.f);
        if (bnin >= 0 && mode != 3) {
            int c0 = kp * 2;
            xv.x = mishf((xv.x - st[c0]) * st[64 + c0]);
            xv.y = mishf((xv.y - st[c0 + 1]) * st[64 + c0 + 1]);
        }
        float lx, ly;
        uint32_t h = pack_hi(xv.x, xv.y, lx, ly);
        *(uint32_t*)(smem + SM_A_H + r * STR + kp * 4) = h;
        *(uint32_t*)(smem + SM_A_L + r * STR + kp * 4) = pack_bf2(lx, ly);
    }
    // B tile: Bt[n][k] = W[k][n]; 64 n x 32 k-pairs
    for (int idx = t; idx < 64 * 32; idx += 256) {
        int n = idx >> 5, kp = idx & 31;
        float w0 = W[(kp * 2) * 64 + n];
        float w1 = W[(kp * 2 + 1) * 64 + n];
        float l0, l1;
        uint32_t h = pack_hi(w0, w1, l0, l1);
        *(uint32_t*)(smem + SM_B_H + n * STR + kp * 4) = h;
        *(uint32_t*)(smem + SM_B_L + n * STR + kp * 4) = pack_bf2(l0, l1);
    }
    __syncthreads();

    // warp w: rows (w>>1)*16 + {g, g+8}; cols (w&1)*32 + nc*8
    int mrow = (w >> 1) * 16;
    int nbase = (w & 1) * 32;
    float c[4][4];
#pragma unroll
    for (int nc = 0; nc < 4; nc++)
        c[nc][0] = c[nc][1] = c[nc][2] = c[nc][3] = 0.f;

    const char* Ah = smem + SM_A_H + (mrow + g) * STR + tid * 4;
    const char* Al = smem + SM_A_L + (mrow + g) * STR + tid * 4;
    const char* Bh = smem + SM_B_H + (nbase + g) * STR + tid * 4;
    const char* Bl = smem + SM_B_L + (nbase + g) * STR + tid * 4;
#pragma unroll
    for (int kk = 0; kk < 4; kk++) {
        int ko = kk * 32;  // byte offset of k16 step within row
        uint32_t ah0 = *(const uint32_t*)(Ah + ko);
        uint32_t ah1 = *(const uint32_t*)(Ah + ko + 8 * STR);
        uint32_t ah2 = *(const uint32_t*)(Ah + ko + 16);
        uint32_t ah3 = *(const uint32_t*)(Ah + ko + 8 * STR + 16);
        uint32_t al0 = *(const uint32_t*)(Al + ko);
        uint32_t al1 = *(const uint32_t*)(Al + ko + 8 * STR);
        uint32_t al2 = *(const uint32_t*)(Al + ko + 16);
        uint32_t al3 = *(const uint32_t*)(Al + ko + 8 * STR + 16);
#pragma unroll
        for (int nc = 0; nc < 4; nc++) {
            uint32_t bh0 = *(const uint32_t*)(Bh + nc * 8 * STR + ko);
            uint32_t bh1 = *(const uint32_t*)(Bh + nc * 8 * STR + ko + 16);
            uint32_t bl0 = *(const uint32_t*)(Bl + nc * 8 * STR + ko);
            uint32_t bl1 = *(const uint32_t*)(Bl + nc * 8 * STR + ko + 16);
            mma16816(c[nc], ah0, ah1, ah2, ah3, bh0, bh1);
            mma16816(c[nc], ah0, ah1, ah2, ah3, bl0, bl1);
            mma16816(c[nc], al0, al1, al2, al3, bh0, bh1);
        }
    }
    __syncthreads();  // done reading A/B tiles; stage region may be overwritten

    // stage acc + bias: thread owns rows mrow+g (c0,c1), mrow+g+8 (c2,c3)
    float* stg = (float*)(smem + SM_STAGE);
    int r0l = mrow + g;
#pragma unroll
    for (int nc = 0; nc < 4; nc++) {
        int col = nbase + nc * 8 + tid * 2;
        stg[r0l * 68 + col]           = c[nc][0] + st[128 + col];
        stg[r0l * 68 + col + 1]       = c[nc][1] + st[128 + col + 1];
        stg[(r0l + 8) * 68 + col]     = c[nc][2] + st[128 + col];
        stg[(r0l + 8) * 68 + col + 1] = c[nc][3] + st[128 + col + 1];
    }
    __syncthreads();

    // final transform + global store; rewrite stage with final y (zeros if invalid)
    const float4* R4 = (const float4*)res;
    float4* Y4 = (float4*)Y;
#pragma unroll
    for (int it = 0; it < 4; it++) {
        int idx = t + 256 * it;          // 1024 float4s
        int lr = idx >> 4, c4 = idx & 15;
        int r = row0 + lr;
        bool valid = (r < M);
        float4 y = *(float4*)&stg[lr * 68 + c4 * 4];
        int c0 = c4 * 4;
        if (mode == 2) {
            y.x = mishf(y.x); y.y = mishf(y.y); y.z = mishf(y.z); y.w = mishf(y.w);
        }
        if (mode == 3 && valid) {
            float4 rr = R4[r * 16 + c4];
            if (bnin >= 0) {
                rr.x = mishf((rr.x - st[c0 + 0]) * st[64 + c0 + 0]);
                rr.y = mishf((rr.y - st[c0 + 1]) * st[64 + c0 + 1]);
                rr.z = mishf((rr.z - st[c0 + 2]) * st[64 + c0 + 2]);
                rr.w = mishf((rr.w - st[c0 + 3]) * st[64 + c0 + 3]);
            }
            y.x += rr.x; y.y += rr.y; y.z += rr.z; y.w += rr.w;
        }
        if (!valid) y = make_float4(0.f, 0.f, 0.f, 0.f);
        *(float4*)&stg[lr * 68 + c4 * 4] = y;
        if (valid) Y4[r * 16 + c4] = y;
    }
    __syncthreads();

    if (mode == 3 && t < 64) {
        float s = 0.f, q = 0.f;
#pragma unroll 8
        for (int rr = 0; rr < 64; rr++) {
            float v = stg[rr * 68 + t];
            s += v; q += v * v;
        }
        atomicAdd(&g_bnsum[layer * DD + t], s);
        atomicAdd(&g_bnsq[layer * DD + t], q);
    }
}

// ---------------- aggregation in p-space, fused mish + replica mean ----------------
#define AGG_ACC(m, v) { \
    if ((m) & 1u) { a0.x += (v).x; a0.y += (v).y; } \
    if ((m) & 2u) { a1.x += (v).x; a1.y += (v).y; } \
    if ((m) & 4u) { a2.x += (v).x; a2.y += (v).y; } \
    if ((m) & 8u) { a3.x += (v).x; a3.y += (v).y; } }

__global__ __launch_bounds__(256) void agg_kernel(
    const float2* __restrict__ p2, const unsigned char* __restrict__ keepb,
    const float* __restrict__ b1, float2* __restrict__ tbar) {
    int gt = blockIdx.x * blockDim.x + threadIdx.x;
    int n = gt >> 5;
    int lane = gt & 31;
    if (n >= NN) return;
    unsigned mb = keepb[n];
    float2 vs = p2[n * 32 + lane];
    float2 a0, a1, a2, a3;
    a0.x = (mb & 1u) ? vs.x : 0.f; a0.y = (mb & 1u) ? vs.y : 0.f;
    a1.x = (mb & 2u) ? vs.x : 0.f; a1.y = (mb & 2u) ? vs.y : 0.f;
    a2.x = (mb & 4u) ? vs.x : 0.f; a2.y = (mb & 4u) ? vs.y : 0.f;
    a3.x = (mb & 8u) ? vs.x : 0.f; a3.y = (mb & 8u) ? vs.y : 0.f;
    int j = g_rowptr[n], end = g_rowptr[n + 1];
    for (; j + 3 < end; j += 4) {
        int s0 = g_col[j], s1 = g_col[j + 1], s2 = g_col[j + 2], s3 = g_col[j + 3];
        unsigned m0 = keepb[s0], m1 = keepb[s1], m2 = keepb[s2], m3 = keepb[s3];
        float2 v0 = p2[s0 * 32 + lane];
        float2 v1 = p2[s1 * 32 + lane];
        float2 v2 = p2[s2 * 32 + lane];
        float2 v3 = p2[s3 * 32 + lane];
        AGG_ACC(m0, v0) AGG_ACC(m1, v1) AGG_ACC(m2, v2) AGG_ACC(m3, v3)
    }
    for (; j < end; j++) {
        int s = g_col[j];
        unsigned m = keepb[s];
        float2 v = p2[s * 32 + lane];
        AGG_ACC(m, v)
    }
    float bx = b1[2 * lane], by = b1[2 * lane + 1];
    float sx = mishf(a0.x + bx) + mishf(a1.x + bx) + mishf(a2.x + bx) + mishf(a3.x + bx);
    float sy = mishf(a0.y + by) + mishf(a1.y + by) + mishf(a2.y + by) + mishf(a3.y + by);
    float2 o;
    o.x = 0.25f * sx;
    o.y = 0.25f * sy;
    tbar[n * 32 + lane] = o;
}

// ---------------- final: out = xproj + mish(bn(hnew, slot LL-1)) ----------------
__global__ __launch_bounds__(256) void bn_final(float* __restrict__ dst) {
    __shared__ float st[128];
    int t = threadIdx.x;
    if (t < 64) {
        float mu = g_bnsum[(LL - 1) * DD + t] * (1.f / NN);
        float var = g_bnsq[(LL - 1) * DD + t] * (1.f / NN) - mu * mu;
        st[t] = mu;
        st[64 + t] = rsqrtf(var + 1e-5f);
    }
    __syncthreads();
    int base = blockIdx.x * 1024;
    const float4* H4 = (const float4*)g_hnew;
    const float4* X4 = (const float4*)g_xproj;
    float4* D4 = (float4*)dst;
#pragma unroll
    for (int q = 0; q < 4; q++) {
        int idx = base + t + 256 * q;
        int r = idx >> 4;
        if (r >= NN) break;
        int c0 = (idx & 15) * 4;
        float4 v = H4[idx];
        float4 xp = X4[idx];
        v.x = xp.x + mishf((v.x - st[c0 + 0]) * st[64 + c0 + 0]);
        v.y = xp.y + mishf((v.y - st[c0 + 1]) * st[64 + c0 + 1]);
        v.z = xp.z + mishf((v.z - st[c0 + 2]) * st[64 + c0 + 2]);
        v.w = xp.w + mishf((v.w - st[c0 + 3]) * st[64 + c0 + 3]);
        D4[idx] = v;
    }
}

// ---------------- launch ----------------
extern "C" void kernel_launch(void* const* d_in, const int* in_sizes, int n_in,
                              void* d_out, int out_size) {
    const float* x    = (const float*)d_in[0];
    const void*  ei   = d_in[1];  // int32 or int64, auto-detected on device
    const float* nW1  = (const float*)d_in[2];
    const float* nb1  = (const float*)d_in[3];
    const float* nW2  = (const float*)d_in[4];
    const float* nb2  = (const float*)d_in[5];
    const float* cW1  = (const float*)d_in[6];
    const float* cb1  = (const float*)d_in[7];
    const float* cW2  = (const float*)d_in[8];
    const float* cb2  = (const float*)d_in[9];
    float* out = (float*)d_out;

    float *xproj, *p, *tbar, *hnew;
    unsigned char* keepb;
    cudaGetSymbolAddress((void**)&xproj, g_xproj);
    cudaGetSymbolAddress((void**)&p, g_p);
    cudaGetSymbolAddress((void**)&tbar, g_tbar);
    cudaGetSymbolAddress((void**)&hnew, g_hnew);
    cudaGetSymbolAddress((void**)&keepb, g_keepb);

    cudaFuncSetAttribute(mma_gemm, cudaFuncAttributeMaxDynamicSharedMemorySize, SM_TOTAL);

    const int TB = 256;
    const int EB = (EE + TB - 1) / TB;
    const int TGB = (NN + 63) / 64;

    initdetect_mask<<<EB, TB>>>((const unsigned*)ei);
    count_deg<<<EB, TB>>>(ei);
    scan_one<<<1, 1024>>>();
    // node MLP first (independent of CSR) — places mma_gemm at the ncu capture slot
    mma_gemm<<<TGB, 256, SM_TOTAL>>>(x, nW1, nb1, nullptr, p, NN, 2, -1, 0);
    mma_gemm<<<TGB, 256, SM_TOTAL>>>(p, nW2, nb2, nullptr, xproj, NN, 1, -1, 0);
    fill_csr<<<EB, TB>>>(ei);

    for (int l = 0; l < LL; l++) {
        const float* hsrc = (l == 0) ? xproj : hnew;
        mma_gemm<<<TGB, 256, SM_TOTAL>>>(hsrc, cW1 + l * DD * DD, nullptr, nullptr, p, NN, 0, l - 1, l);
        agg_kernel<<<(NN * 32 + TB - 1) / TB, TB>>>(
            (const float2*)p, keepb + l * NN, cb1 + l * DD, (float2*)tbar);
        mma_gemm<<<TGB, 256, SM_TOTAL>>>(tbar, cW2 + l * DD * DD, cb2 + l * DD, hsrc, hnew, NN, 3, l - 1, l);
    }
    bn_final<<<(NN + 63) / 64, 256>>>(out);
}

// round 16
// speedup vs baseline: 1.1682x; 1.1682x over previous
#include <cuda_runtime.h>
#include <cstdint>

#define NN 50000
#define EE 800000
#define DD 64
#define LL 3
#define RR 4

// ---------------- device scratch (static: no allocations allowed) ----------------
__device__ float g_xproj[NN * DD];
__device__ float g_p[NN * DD];
__device__ float g_tbar[NN * DD];
__device__ float g_hnew[NN * DD];
__device__ unsigned char g_keepb[LL * NN];
__device__ int g_deg[NN];
__device__ int g_rowptr[NN + 1];
__device__ int g_cursor[NN];
__device__ int g_col[EE];
__device__ float g_bnsum[LL * DD];
__device__ float g_bnsq[LL * DD];
__device__ int g_found32;  // sticky: 1 if edge_index is int32. Never reset -> deterministic.

// ---------------- helpers ----------------
__device__ __forceinline__ unsigned rotl32(unsigned v, int s) {
    return (v << s) | (v >> (32 - s));
}

// JAX threefry2x32 (20 rounds), exact
__device__ void threefry(unsigned k0, unsigned k1, unsigned x0, unsigned x1,
                         unsigned& o0, unsigned& o1) {
    unsigned ks2 = k0 ^ k1 ^ 0x1BD11BDAu;
    x0 += k0; x1 += k1;
#define TFR(r) { x0 += x1; x1 = rotl32(x1, r); x1 ^= x0; }
    TFR(13) TFR(15) TFR(26) TFR(6)   x0 += k1;  x1 += ks2 + 1u;
    TFR(17) TFR(29) TFR(16) TFR(24)  x0 += ks2; x1 += k0 + 2u;
    TFR(13) TFR(15) TFR(26) TFR(6)   x0 += k0;  x1 += k1 + 3u;
    TFR(17) TFR(29) TFR(16) TFR(24)  x0 += k1;  x1 += ks2 + 4u;
    TFR(13) TFR(15) TFR(26) TFR(6)   x0 += ks2; x1 += k0 + 5u;
#undef TFR
    o0 = x0; o1 = x1;
}

__device__ __forceinline__ float mishf(float x) {
    float sp = fmaxf(x, 0.f) + log1pf(expf(-fabsf(x)));
    return x * tanhf(sp);
}

__device__ __forceinline__ int edge_val(const void* ei, int idx) {
    if (g_found32 == 0) return (int)((const long long*)ei)[idx];
    return ((const int*)ei)[idx];
}

// BN stats for slot into smem st[0..63]=mu, st[64..127]=rstd (first 64 threads)
__device__ __forceinline__ void load_bnstats(float* st, int slot, int t) {
    if (slot >= 0 && t < 64) {
        float mu = g_bnsum[slot * DD + t] * (1.f / NN);
        float var = g_bnsq[slot * DD + t] * (1.f / NN) - mu * mu;
        st[t] = mu;
        st[64 + t] = rsqrtf(var + 1e-5f);
    }
}

// ---------------- init + dtype detect + bn zero + dropout masks (merged) ----------
// jax_threefry_partitionable=True random_bits (bit_width 32): draw = o0 ^ o1 of
// threefry(key, f>>32, (u32)f); u = bitcast(draw>>9 | 0x3f800000)-1; keep = !(u<0.2).
__global__ void initdetect_mask(const unsigned* w) {
    int i = blockIdx.x * blockDim.x + threadIdx.x;
    if (i < EE && w[2 * i + 1] != 0u) g_found32 = 1;
    if (i < NN) g_deg[i] = 0;
    if (i < LL * DD) { g_bnsum[i] = 0.f; g_bnsq[i] = 0.f; }
    if (i < LL * NN) {
        int lay = i / NN, n = i % NN;
        unsigned fk0, fk1;
        threefry(0u, 42u, 0u, (unsigned)lay, fk0, fk1);  // fold_in(key(42), lay)
        unsigned byte = 0;
#pragma unroll
        for (int r = 0; r < RR; r++) {
            unsigned o0, o1;
            threefry(fk0, fk1, 0u, (unsigned)(r * NN + n), o0, o1);
            unsigned draw = o0 ^ o1;
            float u = __uint_as_float((draw >> 9) | 0x3f800000u) - 1.0f;
            if (!(u < 0.2f)) byte |= (1u << r);
        }
        g_keepb[i] = (unsigned char)byte;
    }
}

// ---------------- CSR build ----------------
__global__ void count_deg(const void* ei) {
    int e = blockIdx.x * blockDim.x + threadIdx.x;
    if (e < EE) atomicAdd(&g_deg[edge_val(ei, EE + e)], 1);
}

// single-block chunked exclusive scan of g_deg -> g_rowptr, g_cursor
__global__ __launch_bounds__(1024) void scan_one() {
    __shared__ int s[1024];
    __shared__ int carry_s;
    int t = threadIdx.x;
    if (t == 0) carry_s = 0;
    __syncthreads();
    for (int c = 0; c < 13; c++) {
        int base = c * 4096 + t * 4;
        int v0 = (base + 0 < NN) ? g_deg[base + 0] : 0;
        int v1 = (base + 1 < NN) ? g_deg[base + 1] : 0;
        int v2 = (base + 2 < NN) ? g_deg[base + 2] : 0;
        int v3 = (base + 3 < NN) ? g_deg[base + 3] : 0;
        int sum = v0 + v1 + v2 + v3;
        s[t] = sum;
        __syncthreads();
#pragma unroll
        for (int off = 1; off < 1024; off <<= 1) {
            int x = (t >= off) ? s[t - off] : 0;
            __syncthreads();
            s[t] += x;
            __syncthreads();
        }
        int excl = s[t] - sum + carry_s;
        if (base + 0 < NN) { g_rowptr[base + 0] = excl;            g_cursor[base + 0] = excl; }
        if (base + 1 < NN) { g_rowptr[base + 1] = excl + v0;       g_cursor[base + 1] = excl + v0; }
        if (base + 2 < NN) { g_rowptr[base + 2] = excl + v0 + v1;  g_cursor[base + 2] = excl + v0 + v1; }
        if (base + 3 < NN) { g_rowptr[base + 3] = excl + v0 + v1 + v2;
                             g_cursor[base + 3] = excl + v0 + v1 + v2; }
        __syncthreads();
        if (t == 0) carry_s += s[1023];
        __syncthreads();
    }
    if (t == 0) g_rowptr[NN] = EE;
}

__global__ void fill_csr(const void* ei) {
    int e = blockIdx.x * blockDim.x + threadIdx.x;
    if (e < EE) {
        int dst = edge_val(ei, EE + e);
        int src = edge_val(ei, e);
        int pos = atomicAdd(&g_cursor[dst], 1);
        g_col[pos] = src;
    }
}

// ---------------- GEMM (M x 64) @ (64 x 64), 8x4 register tile, fused epilogues ---
// 128 threads: tx = t&15 (cols tx*4), ty = t>>4 (rows ty*8..+7). 64-row tile/block.
// Per k: 1 W float4 + 8 broadcast X scalars -> ~80KB smem/block (was 512KB @4x4).
// mode 0: Y = X@W ; 1: +b ; 2: mish(+b) ; 3: +b + BN(res) + bn stats (slot layer)
// bnin >= 0: X transformed mish((x-mu)*rstd) on load (modes 0/1/2); in mode 3 the
// transform applies to res instead.
#define XSTR 68  /* Xs row stride in floats (pad kills bank conflicts) */
__global__ __launch_bounds__(128) void gemm64(
    const float* __restrict__ X, const float* __restrict__ W,
    const float* __restrict__ bias, const float* __restrict__ res,
    float* __restrict__ Y, int M, int mode, int bnin, int layer) {
    __shared__ float Xs[64 * XSTR];
    __shared__ float Ws[64 * 64];
    __shared__ float st[128];
    __shared__ float s_sum[64];
    __shared__ float s_sq[64];
    int t = threadIdx.x;
    int row0 = blockIdx.x * 64;

    load_bnstats(st, bnin, t);
    if (mode == 3 && t < 64) { s_sum[t] = 0.f; s_sq[t] = 0.f; }
    const float4* W4 = (const float4*)W;
    float4* Ws4 = (float4*)Ws;
#pragma unroll
    for (int i = 0; i < 8; i++) Ws4[t + 128 * i] = W4[t + 128 * i];
    __syncthreads();  // st ready before X transform

    const float4* X4 = (const float4*)X;
#pragma unroll
    for (int i = 0; i < 8; i++) {
        int idx = t + 128 * i;          // 1024 float4s
        int lr = idx >> 4;
        int c4 = idx & 15;
        int r = row0 + lr;
        float4 xv = (r < M) ? X4[r * 16 + c4] : make_float4(0.f, 0.f, 0.f, 0.f);
        if (bnin >= 0 && mode != 3) {
            int c0 = c4 * 4;
            xv.x = mishf((xv.x - st[c0 + 0]) * st[64 + c0 + 0]);
            xv.y = mishf((xv.y - st[c0 + 1]) * st[64 + c0 + 1]);
            xv.z = mishf((xv.z - st[c0 + 2]) * st[64 + c0 + 2]);
            xv.w = mishf((xv.w - st[c0 + 3]) * st[64 + c0 + 3]);
        }
        *(float4*)&Xs[lr * XSTR + c4 * 4] = xv;
    }
    __syncthreads();

    int tx = t & 15, ty = t >> 4;
    float acc[8][4];
#pragma unroll
    for (int i = 0; i < 8; i++)
        acc[i][0] = acc[i][1] = acc[i][2] = acc[i][3] = 0.f;
#pragma unroll 4
    for (int k = 0; k < 64; k++) {
        float4 w = Ws4[k * 16 + tx];
#pragma unroll
        for (int i = 0; i < 8; i++) {
            float xv = Xs[(ty * 8 + i) * XSTR + k];
            acc[i][0] = fmaf(xv, w.x, acc[i][0]);
            acc[i][1] = fmaf(xv, w.y, acc[i][1]);
            acc[i][2] = fmaf(xv, w.z, acc[i][2]);
            acc[i][3] = fmaf(xv, w.w, acc[i][3]);
        }
    }
    float4 b = bias ? ((const float4*)bias)[tx] : make_float4(0.f, 0.f, 0.f, 0.f);
    float4* Y4 = (float4*)Y;
    const float4* R4 = (const float4*)res;
    int c0 = tx * 4;
    float lsum[4] = {0.f, 0.f, 0.f, 0.f}, lsq[4] = {0.f, 0.f, 0.f, 0.f};
#pragma unroll
    for (int i = 0; i < 8; i++) {
        int r = row0 + ty * 8 + i;
        if (r >= M) break;
        float4 y;
        y.x = acc[i][0] + b.x; y.y = acc[i][1] + b.y;
        y.z = acc[i][2] + b.z; y.w = acc[i][3] + b.w;
        if (mode == 2) {
            y.x = mishf(y.x); y.y = mishf(y.y);
            y.z = mishf(y.z); y.w = mishf(y.w);
        }
        if (mode == 3) {
            float4 rr = R4[r * 16 + tx];
            if (bnin >= 0) {
                rr.x = mishf((rr.x - st[c0 + 0]) * st[64 + c0 + 0]);
                rr.y = mishf((rr.y - st[c0 + 1]) * st[64 + c0 + 1]);
                rr.z = mishf((rr.z - st[c0 + 2]) * st[64 + c0 + 2]);
                rr.w = mishf((rr.w - st[c0 + 3]) * st[64 + c0 + 3]);
            }
            y.x += rr.x; y.y += rr.y; y.z += rr.z; y.w += rr.w;
            lsum[0] += y.x; lsum[1] += y.y; lsum[2] += y.z; lsum[3] += y.w;
            lsq[0] += y.x * y.x; lsq[1] += y.y * y.y;
            lsq[2] += y.z * y.z; lsq[3] += y.w * y.w;
        }
        Y4[r * 16 + tx] = y;
    }
    if (mode == 3) {
#pragma unroll
        for (int j = 0; j < 4; j++) {
            atomicAdd(&s_sum[c0 + j], lsum[j]);
            atomicAdd(&s_sq[c0 + j], lsq[j]);
        }
        __syncthreads();
        if (t < 64) {
            atomicAdd(&g_bnsum[layer * DD + t], s_sum[t]);
            atomicAdd(&g_bnsq[layer * DD + t], s_sq[t]);
        }
    }
}

// ---------------- aggregation in p-space, fused mish + replica mean ----------------
// One warp per node; lane handles 2 features. 4-wide software pipeline for MLP.
#define AGG_ACC(m, v) { \
    if ((m) & 1u) { a0.x += (v).x; a0.y += (v).y; } \
    if ((m) & 2u) { a1.x += (v).x; a1.y += (v).y; } \
    if ((m) & 4u) { a2.x += (v).x; a2.y += (v).y; } \
    if ((m) & 8u) { a3.x += (v).x; a3.y += (v).y; } }

__global__ __launch_bounds__(256) void agg_kernel(
    const float2* __restrict__ p2, const unsigned char* __restrict__ keepb,
    const float* __restrict__ b1, float2* __restrict__ tbar) {
    int gt = blockIdx.x * blockDim.x + threadIdx.x;
    int n = gt >> 5;
    int lane = gt & 31;
    if (n >= NN) return;
    unsigned mb = keepb[n];
    float2 vs = p2[n * 32 + lane];
    float2 a0, a1, a2, a3;
    a0.x = (mb & 1u) ? vs.x : 0.f; a0.y = (mb & 1u) ? vs.y : 0.f;
    a1.x = (mb & 2u) ? vs.x : 0.f; a1.y = (mb & 2u) ? vs.y : 0.f;
    a2.x = (mb & 4u) ? vs.x : 0.f; a2.y = (mb & 4u) ? vs.y : 0.f;
    a3.x = (mb & 8u) ? vs.x : 0.f; a3.y = (mb & 8u) ? vs.y : 0.f;
    int j = g_rowptr[n], end = g_rowptr[n + 1];
    for (; j + 3 < end; j += 4) {
        int s0 = g_col[j], s1 = g_col[j + 1], s2 = g_col[j + 2], s3 = g_col[j + 3];
        unsigned m0 = keepb[s0], m1 = keepb[s1], m2 = keepb[s2], m3 = keepb[s3];
        float2 v0 = p2[s0 * 32 + lane];
        float2 v1 = p2[s1 * 32 + lane];
        float2 v2 = p2[s2 * 32 + lane];
        float2 v3 = p2[s3 * 32 + lane];
        AGG_ACC(m0, v0) AGG_ACC(m1, v1) AGG_ACC(m2, v2) AGG_ACC(m3, v3)
    }
    for (; j < end; j++) {
        int s = g_col[j];
        unsigned m = keepb[s];
        float2 v = p2[s * 32 + lane];
        AGG_ACC(m, v)
    }
    float bx = b1[2 * lane], by = b1[2 * lane + 1];
    float sx = mishf(a0.x + bx) + mishf(a1.x + bx) + mishf(a2.x + bx) + mishf(a3.x + bx);
    float sy = mishf(a0.y + by) + mishf(a1.y + by) + mishf(a2.y + by) + mishf(a3.y + by);
    float2 o;
    o.x = 0.25f * sx;
    o.y = 0.25f * sy;
    tbar[n * 32 + lane] = o;
}

// ---------------- final: out = xproj + mish(bn(hnew, slot LL-1)) ----------------
__global__ __launch_bounds__(256) void bn_final(float* __restrict__ dst) {
    __shared__ float st[128];
    int t = threadIdx.x;
    load_bnstats(st, LL - 1, t);
    __syncthreads();
    int base = blockIdx.x * 1024;
    const float4* H4 = (const float4*)g_hnew;
    const float4* X4 = (const float4*)g_xproj;
    float4* D4 = (float4*)dst;
#pragma unroll
    for (int q = 0; q < 4; q++) {
        int idx = base + t + 256 * q;
        int r = idx >> 4;
        if (r >= NN) break;
        int c0 = (idx & 15) * 4;
        float4 v = H4[idx];
        float4 xp = X4[idx];
        v.x = xp.x + mishf((v.x - st[c0 + 0]) * st[64 + c0 + 0]);
        v.y = xp.y + mishf((v.y - st[c0 + 1]) * st[64 + c0 + 1]);
        v.z = xp.z + mishf((v.z - st[c0 + 2]) * st[64 + c0 + 2]);
        v.w = xp.w + mishf((v.w - st[c0 + 3]) * st[64 + c0 + 3]);
        D4[idx] = v;
    }
}

// ---------------- launch ----------------
extern "C" void kernel_launch(void* const* d_in, const int* in_sizes, int n_in,
                              void* d_out, int out_size) {
    const float* x    = (const float*)d_in[0];
    const void*  ei   = d_in[1];  // int32 or int64, auto-detected on device
    const float* nW1  = (const float*)d_in[2];
    const float* nb1  = (const float*)d_in[3];
    const float* nW2  = (const float*)d_in[4];
    const float* nb2  = (const float*)d_in[5];
    const float* cW1  = (const float*)d_in[6];
    const float* cb1  = (const float*)d_in[7];
    const float* cW2  = (const float*)d_in[8];
    const float* cb2  = (const float*)d_in[9];
    float* out = (float*)d_out;

    float *xproj, *p, *tbar, *hnew;
    unsigned char* keepb;
    cudaGetSymbolAddress((void**)&xproj, g_xproj);
    cudaGetSymbolAddress((void**)&p, g_p);
    cudaGetSymbolAddress((void**)&tbar, g_tbar);
    cudaGetSymbolAddress((void**)&hnew, g_hnew);
    cudaGetSymbolAddress((void**)&keepb, g_keepb);

    const int TB = 256;
    const int EB = (EE + TB - 1) / TB;
    const int GB = (NN + 63) / 64;

    initdetect_mask<<<EB, TB>>>((const unsigned*)ei);
    count_deg<<<EB, TB>>>(ei);
    scan_one<<<1, 1024>>>();
    // node MLP first (independent of CSR) — places gemm64 at the ncu capture slot
    gemm64<<<GB, 128>>>(x, nW1, nb1, nullptr, p, NN, 2, -1, 0);
    gemm64<<<GB, 128>>>(p, nW2, nb2, nullptr, xproj, NN, 1, -1, 0);
    fill_csr<<<EB, TB>>>(ei);

    for (int l = 0; l < LL; l++) {
        const float* hsrc = (l == 0) ? xproj : hnew;
        // p <- BN_mish(hsrc) @ cW1   (BN on load; slot l-1; l==0 -> raw xproj)
        gemm64<<<GB, 128>>>(hsrc, cW1 + l * DD * DD, nullptr, nullptr, p, NN, 0, l - 1, l);
        agg_kernel<<<(NN * 32 + TB - 1) / TB, TB>>>(
            (const float2*)p, keepb + l * NN, cb1 + l * DD, (float2*)tbar);
        // hnew <- tbar @ cW2 + b2 + BN_mish(hsrc)   + bn stats for slot l
        gemm64<<<GB, 128>>>(tbar, cW2 + l * DD * DD, cb2 + l * DD, hsrc, hnew, NN, 3, l - 1, l);
    }
    bn_final<<<GB, 256>>>(out);
}